// round 2
// baseline (speedup 1.0000x reference)
#include <cuda_runtime.h>

#define Nn      1000
#define INF_    32
#define Hh      128
#define Mm      128
#define DEGc    16
#define Pp      2
#define OUTn    10
#define NSTART  64
#define MAXM    10000
#define QCAP    10016
#define MSGCAP  640
#define THRv    (1.0f - 1e-7f)

typedef unsigned long long ull;

__device__ float g_feats[Nn*Hh];
__device__ float g_msgs[MSGCAP*Mm];

__device__ __forceinline__ ull pack2(float a, float b){
    ull r; asm("mov.b64 %0, {%1,%2};" : "=l"(r) : "f"(a), "f"(b)); return r;
}
__device__ __forceinline__ ull fma2(ull a, ull b, ull c){
    ull d; asm("fma.rn.f32x2 %0, %1, %2, %3;" : "=l"(d) : "l"(a), "l"(b), "l"(c)); return d;
}
__device__ __forceinline__ float lo2(ull a){
    float x, y; asm("mov.b64 {%0,%1}, %2;" : "=f"(x), "=f"(y) : "l"(a)); return x;
}

// ---------------- encoder: feats0 = xa @ enc_w + enc_b ----------------
__global__ void enc_kernel(const float* __restrict__ xa,
                           const float* __restrict__ ew,
                           const float* __restrict__ eb)
{
    __shared__ float sx[INF_];
    int nrow = blockIdx.x;
    if (threadIdx.x < INF_) sx[threadIdx.x] = xa[nrow*INF_ + threadIdx.x];
    __syncthreads();
    int h = threadIdx.x;
    float a = eb[h];
    #pragma unroll
    for (int i = 0; i < INF_; i++) a = fmaf(sx[i], ew[i*Hh + h], a);
    g_feats[nrow*Hh + h] = a;
}

// ---------------- shared layout (float units) ----------------
#define OFF_NSW  0                        // 256*128 floats (as 64-ull rows)
#define OFF_QN   (OFF_NSW + 256*Hh)       // QCAP ints
#define OFF_RED  (OFF_QN  + QCAP)         // 1024 floats (8 rows x 128)
#define OFF_X2   (OFF_RED + 1024)         // 128 ull = 256 floats (splatted ns)
#define OFF_AW   (OFF_X2  + 256)          // 256
#define OFF_ACTP (OFF_AW  + 256)          // 8
#define OFF_NSB  (OFF_ACTP+ 8)            // 128
#define OFF_NMB  (OFF_NSB + 128)          // 128
#define OFF_G    (OFF_NMB + 128)          // 128
#define OFF_TACT (OFF_G   + 128)          // 1000
#define OFF_NB   (OFF_TACT+ Nn)           // 16 ints
#define OFF_CI   (OFF_NB  + 16)           // 8 ints: head,tail,pc,node,e,done
#define OFF_CF   (OFF_CI  + 8)            // 2 floats: act_b, new_act
#define SMEM_FLOATS (OFF_CF + 8)
#define SMEM_BYTES  (SMEM_FLOATS * 4)

__device__ __forceinline__ void scan_q(int l, int head, int tail, int pcnext,
                                       const int* s_qn, const float* s_tact, int* s_ci)
{
    int lim = tail < MAXM ? tail : MAXM;
    bool found = false;
    while (head < lim) {
        int idx = head + l;
        bool v = idx < lim;
        int nodel = v ? s_qn[idx] : 0;
        float ta = v ? s_tact[nodel] : 2.0f;
        unsigned bal = __ballot_sync(0xffffffffu, v && (ta <= THRv));
        if (bal) {
            int f = __ffs(bal) - 1;
            if (l == f) { s_ci[3] = nodel; s_ci[4] = idx; }
            if (l == 0) s_ci[0] = head + f + 1;
            found = true; break;
        }
        head += 32;
    }
    if (l == 0) {
        if (!found) s_ci[5] = 1;
        s_ci[1] = tail;
        s_ci[2] = pcnext;
    }
}

// ---------------- serial queue kernel (1 block, 512 threads) ----------------
__global__ void __launch_bounds__(512, 1) serial_kernel(
    const float* __restrict__ fm,  const int*   __restrict__ nbr,
    const float* __restrict__ nsw, const float* __restrict__ nsb,
    const float* __restrict__ nmw, const float* __restrict__ nmb,
    const float* __restrict__ aw,  const float* __restrict__ ab,
    const float* __restrict__ dw,  const float* __restrict__ db,
    float* __restrict__ out)
{
    extern __shared__ float sm[];
    ull*   s_nsw2 = (ull*)(sm + OFF_NSW);
    int*   s_qn   = (int*)(sm + OFF_QN);
    float* s_red  = sm + OFF_RED;
    ull*   s_red2 = (ull*)s_red;
    ull*   s_x2   = (ull*)(sm + OFF_X2);
    float* s_aw   = sm + OFF_AW;
    float* s_actp = sm + OFF_ACTP;
    float* s_nsb  = sm + OFF_NSB;
    float* s_nmb  = sm + OFF_NMB;
    float* s_g    = sm + OFF_G;
    float* s_tact = sm + OFF_TACT;
    int*   s_nb   = (int*)(sm + OFF_NB);
    int*   s_ci   = (int*)(sm + OFF_CI);
    float* s_cf   = sm + OFF_CF;

    const int t = threadIdx.x;
    const int w = t >> 5, l = t & 31;
    const int j2 = ((w & 1) << 5) | l;   // pair-column 0..63 -> outputs (2*j2, 2*j2+1)
    const int r  = w >> 1;               // k-group 0..7 -> k in [32r, 32r+32)
    const int k  = 32*r + l;             // this thread's x element (NS input index)

    // ---- init ----
    for (int i = t; i < (256*Hh)/4; i += 512)
        ((float4*)(sm + OFF_NSW))[i] = ((const float4*)nsw)[i];
    if (t < 256) s_aw[t] = aw[t];
    if (t < 128) { s_nsb[t] = nsb[t]; s_nmb[t] = nmb[t]; s_g[t] = 0.f; }
    for (int i = t; i < Nn; i += 512) s_tact[i] = 0.f;
    for (int i = t; i < NSTART; i += 512) s_qn[i] = i;
    if (t == 0) { s_ci[5] = 0; s_cf[0] = ab[0]; }

    // nm_w in registers as f32x2
    ull wnm[32];
    #pragma unroll
    for (int i = 0; i < 32; i++) {
        const float2 v = *(const float2*)(nmw + (32*r + i)*Hh + 2*j2);
        wnm[i] = pack2(v.x, v.y);
    }
    __syncthreads();

    // prologue scan
    if (w == 0) scan_q(l, 0, NSTART, 0, s_qn, s_tact, s_ci);
    __syncthreads();

    while (!s_ci[5]) {
        const int node = s_ci[3], e = s_ci[4], pc = s_ci[2];

        // ---- phase 1: NS partials (x loaded direct from global), act partials,
        //               warp15 prefetches neighbor ids ----
        float xg;
        if (k < Hh) xg = g_feats[node*Hh + k];
        else {
            const float* mp = (e < NSTART) ? (fm + e*Mm)
                                           : (g_msgs + ((e - NSTART) >> 4)*Mm);
            xg = mp[k - Hh];
        }
        int nbreg = 0;
        if (w == 15 && l < DEGc) nbreg = nbr[node*DEGc + l];

        {
            ull acc = 0ull;
            const ull* wb = s_nsw2 + (size_t)(32*r)*64 + j2;
            #pragma unroll
            for (int kk = 0; kk < 32; kk++) {
                float xk = __shfl_sync(0xffffffffu, xg, kk);
                acc = fma2(pack2(xk, xk), wb[kk*64], acc);
            }
            s_red2[r*64 + j2] = acc;
        }
        if ((w & 1) == 0) {
            float ap = xg * s_aw[k];
            #pragma unroll
            for (int o = 16; o; o >>= 1) ap += __shfl_xor_sync(0xffffffffu, ap, o);
            if (l == 0) s_actp[r] = ap;
        }
        if (w == 15 && l < DEGc) s_nb[l] = nbreg;
        __syncthreads();

        // ---- phase 2: reduce ns -> relu -> splat to s_x2 ; finalize act ----
        if (t < 128) {
            float v = s_nsb[t];
            #pragma unroll
            for (int rr = 0; rr < 8; rr++) v += s_red[rr*128 + t];
            v = fmaxf(v, 0.f);
            s_x2[t] = pack2(v, v);
        } else if (t == 128) {
            float z = s_cf[0];
            #pragma unroll
            for (int i = 0; i < 8; i++) z += s_actp[i];
            float cand = 1.f / (1.f + expf(-z));
            float ta = s_tact[node];
            float na = (ta + cand > 1.0f) ? (1.0f - ta) : cand;
            s_cf[1] = na;
            s_tact[node] = ta + na;
        }
        __syncthreads();

        // ---- phase 3: NM partials (weights in regs) ----
        {
            ull acc = 0ull;
            if (r < 4) {
                const ull* xs = s_x2 + 32*r;
                #pragma unroll
                for (int kk = 0; kk < 32; kk++)
                    acc = fma2(xs[kk], wnm[kk], acc);      // uniform LDS.64 broadcast
            } else {
                #pragma unroll
                for (int kk = 0; kk < 32; kk++) {
                    float xk = __shfl_sync(0xffffffffu, xg, kk);  // msg half reused
                    acc = fma2(pack2(xk, xk), wnm[kk], acc);
                }
            }
            s_red2[r*64 + j2] = acc;
        }
        __syncthreads();

        // ---- phase 4: commit (warps 4-11) || enqueue+scan (warp 0) ----
        if (w == 0) {
            int tail = s_ci[1];
            if (l < DEGc && tail + l < QCAP) s_qn[tail + l] = s_nb[l];
            scan_q(l, s_ci[0], tail + DEGc, pc + 1, s_qn, s_tact, s_ci);
        } else if (w >= 4 && w < 8) {
            int idx = t - 128;
            float v = s_nmb[idx];
            #pragma unroll
            for (int rr = 0; rr < 8; rr++) v += s_red[rr*128 + idx];
            if (pc < MSGCAP) g_msgs[pc*Mm + idx] = v;
        } else if (w >= 8 && w < 12) {
            int idx = t - 256;
            float nsv = lo2(s_x2[idx]);
            g_feats[node*Hh + idx] = nsv;
            s_g[idx] += nsv * s_cf[1];
        }
        __syncthreads();
    }

    // ---- decode: logits = g @ dec_w + dec_b, then log_softmax ----
    if (t < Pp*OUTn) {
        int p = t / OUTn, o = t % OUTn;
        float z = db[p*OUTn + o];
        #pragma unroll 8
        for (int h = 0; h < Hh; h++) z = fmaf(s_g[h], dw[(p*Hh + h)*OUTn + o], z);
        s_red[t] = z;
    }
    __syncthreads();
    if (t < Pp) {
        float mx = -1e30f;
        for (int o = 0; o < OUTn; o++) mx = fmaxf(mx, s_red[t*OUTn + o]);
        float se = 0.f;
        for (int o = 0; o < OUTn; o++) se += expf(s_red[t*OUTn + o] - mx);
        float ls = logf(se);
        for (int o = 0; o < OUTn; o++) out[t*OUTn + o] = s_red[t*OUTn + o] - mx - ls;
    }
}

extern "C" void kernel_launch(void* const* d_in, const int* in_sizes, int n_in,
                              void* d_out, int out_size)
{
    const float* xa  = (const float*)d_in[0];
    const float* fm  = (const float*)d_in[1];
    const int*   nbv = (const int*)  d_in[2];
    // d_in[3] = num_starts (compile-time 64 for this problem)
    const float* ew  = (const float*)d_in[4];
    const float* eb  = (const float*)d_in[5];
    const float* nsw = (const float*)d_in[6];
    const float* nsb = (const float*)d_in[7];
    const float* nmw = (const float*)d_in[8];
    const float* nmb = (const float*)d_in[9];
    const float* aw  = (const float*)d_in[10];
    const float* ab  = (const float*)d_in[11];
    const float* dw  = (const float*)d_in[12];
    const float* db  = (const float*)d_in[13];
    float* out = (float*)d_out;

    cudaFuncSetAttribute(serial_kernel,
                         cudaFuncAttributeMaxDynamicSharedMemorySize, SMEM_BYTES);

    enc_kernel<<<Nn, Hh>>>(xa, ew, eb);
    serial_kernel<<<1, 512, SMEM_BYTES>>>(fm, nbv, nsw, nsb, nmw, nmb,
                                          aw, ab, dw, db, out);
}

// round 3
// speedup vs baseline: 1.0012x; 1.0012x over previous
#include <cuda_runtime.h>

#define Nn      1000
#define INF_    32
#define Hh      128
#define Mm      128
#define DEGc    16
#define Pp      2
#define OUTn    10
#define NSTART  64
#define MAXM    10000
#define QCAP    10016
#define MSGCAP  640
#define THRv    (1.0f - 1e-7f)

typedef unsigned long long ull;

__device__ float g_feats[Nn*Hh];
__device__ float g_msgs[MSGCAP*Mm];

__device__ __forceinline__ ull pack2(float a, float b){
    ull r; asm("mov.b64 %0, {%1,%2};" : "=l"(r) : "f"(a), "f"(b)); return r;
}
__device__ __forceinline__ ull fma2(ull a, ull b, ull c){
    ull d; asm("fma.rn.f32x2 %0, %1, %2, %3;" : "=l"(d) : "l"(a), "l"(b), "l"(c)); return d;
}
__device__ __forceinline__ float lo2(ull a){
    float x, y; asm("mov.b64 {%0,%1}, %2;" : "=f"(x), "=f"(y) : "l"(a)); return x;
}

// ---------------- encoder: feats0 = xa @ enc_w + enc_b ----------------
__global__ void enc_kernel(const float* __restrict__ xa,
                           const float* __restrict__ ew,
                           const float* __restrict__ eb)
{
    __shared__ float sx[INF_];
    int nrow = blockIdx.x;
    if (threadIdx.x < INF_) sx[threadIdx.x] = xa[nrow*INF_ + threadIdx.x];
    __syncthreads();
    int h = threadIdx.x;
    float a = eb[h];
    #pragma unroll
    for (int i = 0; i < INF_; i++) a = fmaf(sx[i], ew[i*Hh + h], a);
    g_feats[nrow*Hh + h] = a;
}

// ---------------- shared layout (float units) ----------------
#define OFF_NSW  0                        // 256*128 floats (as 64-ull rows)
#define OFF_QN   (OFF_NSW + 256*Hh)       // QCAP ints
#define OFF_RED  (OFF_QN  + QCAP)         // 1024 floats (8 rows x 128)
#define OFF_X2   (OFF_RED + 1024)         // 128 ull = 256 floats (splatted ns)
#define OFF_AW   (OFF_X2  + 256)          // 256
#define OFF_ACTP (OFF_AW  + 256)          // 8
#define OFF_NSB  (OFF_ACTP+ 8)            // 128
#define OFF_NMB  (OFF_NSB + 128)          // 128
#define OFF_G    (OFF_NMB + 128)          // 128
#define OFF_TACT (OFF_G   + 128)          // 1000
#define OFF_NB   (OFF_TACT+ Nn)           // 16 ints
#define OFF_CI   (OFF_NB  + 16)           // 8 ints: head,tail,pc,node,e,done
#define OFF_CF   (OFF_CI  + 8)            // 2 floats: act_b, new_act
#define SMEM_FLOATS (OFF_CF + 8)
#define SMEM_BYTES  (SMEM_FLOATS * 4)

__device__ __forceinline__ void scan_q(int l, int head, int tail, int pcnext,
                                       const int* s_qn, const float* s_tact, int* s_ci)
{
    int lim = tail < MAXM ? tail : MAXM;
    bool found = false;
    while (head < lim) {
        int idx = head + l;
        bool v = idx < lim;
        int nodel = v ? s_qn[idx] : 0;
        float ta = v ? s_tact[nodel] : 2.0f;
        unsigned bal = __ballot_sync(0xffffffffu, v && (ta <= THRv));
        if (bal) {
            int f = __ffs(bal) - 1;
            if (l == f) { s_ci[3] = nodel; s_ci[4] = idx; }
            if (l == 0) s_ci[0] = head + f + 1;
            found = true; break;
        }
        head += 32;
    }
    if (l == 0) {
        if (!found) s_ci[5] = 1;
        s_ci[1] = tail;
        s_ci[2] = pcnext;
    }
}

// ---------------- serial queue kernel (1 block, 512 threads) ----------------
__global__ void __launch_bounds__(512, 1) serial_kernel(
    const float* __restrict__ fm,  const int*   __restrict__ nbr,
    const float* __restrict__ nsw, const float* __restrict__ nsb,
    const float* __restrict__ nmw, const float* __restrict__ nmb,
    const float* __restrict__ aw,  const float* __restrict__ ab,
    const float* __restrict__ dw,  const float* __restrict__ db,
    float* __restrict__ out)
{
    extern __shared__ float sm[];
    ull*   s_nsw2 = (ull*)(sm + OFF_NSW);
    int*   s_qn   = (int*)(sm + OFF_QN);
    float* s_red  = sm + OFF_RED;
    ull*   s_red2 = (ull*)s_red;
    ull*   s_x2   = (ull*)(sm + OFF_X2);
    float* s_aw   = sm + OFF_AW;
    float* s_actp = sm + OFF_ACTP;
    float* s_nsb  = sm + OFF_NSB;
    float* s_nmb  = sm + OFF_NMB;
    float* s_g    = sm + OFF_G;
    float* s_tact = sm + OFF_TACT;
    int*   s_nb   = (int*)(sm + OFF_NB);
    int*   s_ci   = (int*)(sm + OFF_CI);
    float* s_cf   = sm + OFF_CF;

    const int t = threadIdx.x;
    const int w = t >> 5, l = t & 31;
    const int j2 = ((w & 1) << 5) | l;   // pair-column 0..63 -> outputs (2*j2, 2*j2+1)
    const int r  = w >> 1;               // k-group 0..7 -> k in [32r, 32r+32)
    const int k  = 32*r + l;             // this thread's x element (NS input index)

    // ---- init ----
    for (int i = t; i < (256*Hh)/4; i += 512)
        ((float4*)(sm + OFF_NSW))[i] = ((const float4*)nsw)[i];
    if (t < 256) s_aw[t] = aw[t];
    if (t < 128) { s_nsb[t] = nsb[t]; s_nmb[t] = nmb[t]; s_g[t] = 0.f; }
    for (int i = t; i < Nn; i += 512) s_tact[i] = 0.f;
    for (int i = t; i < NSTART; i += 512) s_qn[i] = i;
    if (t == 0) { s_ci[5] = 0; s_cf[0] = ab[0]; }

    // nm_w in registers as f32x2
    ull wnm[32];
    #pragma unroll
    for (int i = 0; i < 32; i++) {
        const float2 v = *(const float2*)(nmw + (32*r + i)*Hh + 2*j2);
        wnm[i] = pack2(v.x, v.y);
    }
    __syncthreads();

    // prologue scan
    if (w == 0) scan_q(l, 0, NSTART, 0, s_qn, s_tact, s_ci);
    __syncthreads();

    while (!s_ci[5]) {
        const int node = s_ci[3], e = s_ci[4], pc = s_ci[2];

        // ---- phase 1: NS partials (x loaded direct from global), act partials,
        //               warp15 prefetches neighbor ids ----
        float xg;
        if (k < Hh) xg = g_feats[node*Hh + k];
        else {
            const float* mp = (e < NSTART) ? (fm + e*Mm)
                                           : (g_msgs + ((e - NSTART) >> 4)*Mm);
            xg = mp[k - Hh];
        }
        int nbreg = 0;
        if (w == 15 && l < DEGc) nbreg = nbr[node*DEGc + l];

        {
            ull acc = 0ull;
            const ull* wb = s_nsw2 + (size_t)(32*r)*64 + j2;
            #pragma unroll
            for (int kk = 0; kk < 32; kk++) {
                float xk = __shfl_sync(0xffffffffu, xg, kk);
                acc = fma2(pack2(xk, xk), wb[kk*64], acc);
            }
            s_red2[r*64 + j2] = acc;
        }
        if ((w & 1) == 0) {
            float ap = xg * s_aw[k];
            #pragma unroll
            for (int o = 16; o; o >>= 1) ap += __shfl_xor_sync(0xffffffffu, ap, o);
            if (l == 0) s_actp[r] = ap;
        }
        if (w == 15 && l < DEGc) s_nb[l] = nbreg;
        __syncthreads();

        // ---- phase 2: reduce ns -> relu -> splat to s_x2 ; finalize act ----
        if (t < 128) {
            float v = s_nsb[t];
            #pragma unroll
            for (int rr = 0; rr < 8; rr++) v += s_red[rr*128 + t];
            v = fmaxf(v, 0.f);
            s_x2[t] = pack2(v, v);
        } else if (t == 128) {
            float z = s_cf[0];
            #pragma unroll
            for (int i = 0; i < 8; i++) z += s_actp[i];
            float cand = 1.f / (1.f + expf(-z));
            float ta = s_tact[node];
            float na = (ta + cand > 1.0f) ? (1.0f - ta) : cand;
            s_cf[1] = na;
            s_tact[node] = ta + na;
        }
        __syncthreads();

        // ---- phase 3: NM partials (weights in regs) ----
        {
            ull acc = 0ull;
            if (r < 4) {
                const ull* xs = s_x2 + 32*r;
                #pragma unroll
                for (int kk = 0; kk < 32; kk++)
                    acc = fma2(xs[kk], wnm[kk], acc);      // uniform LDS.64 broadcast
            } else {
                #pragma unroll
                for (int kk = 0; kk < 32; kk++) {
                    float xk = __shfl_sync(0xffffffffu, xg, kk);  // msg half reused
                    acc = fma2(pack2(xk, xk), wnm[kk], acc);
                }
            }
            s_red2[r*64 + j2] = acc;
        }
        __syncthreads();

        // ---- phase 4: commit (warps 4-11) || enqueue+scan (warp 0) ----
        if (w == 0) {
            int tail = s_ci[1];
            if (l < DEGc && tail + l < QCAP) s_qn[tail + l] = s_nb[l];
            scan_q(l, s_ci[0], tail + DEGc, pc + 1, s_qn, s_tact, s_ci);
        } else if (w >= 4 && w < 8) {
            int idx = t - 128;
            float v = s_nmb[idx];
            #pragma unroll
            for (int rr = 0; rr < 8; rr++) v += s_red[rr*128 + idx];
            if (pc < MSGCAP) g_msgs[pc*Mm + idx] = v;
        } else if (w >= 8 && w < 12) {
            int idx = t - 256;
            float nsv = lo2(s_x2[idx]);
            g_feats[node*Hh + idx] = nsv;
            s_g[idx] += nsv * s_cf[1];
        }
        __syncthreads();
    }

    // ---- decode: logits = g @ dec_w + dec_b, then log_softmax ----
    if (t < Pp*OUTn) {
        int p = t / OUTn, o = t % OUTn;
        float z = db[p*OUTn + o];
        #pragma unroll 8
        for (int h = 0; h < Hh; h++) z = fmaf(s_g[h], dw[(p*Hh + h)*OUTn + o], z);
        s_red[t] = z;
    }
    __syncthreads();
    if (t < Pp) {
        float mx = -1e30f;
        for (int o = 0; o < OUTn; o++) mx = fmaxf(mx, s_red[t*OUTn + o]);
        float se = 0.f;
        for (int o = 0; o < OUTn; o++) se += expf(s_red[t*OUTn + o] - mx);
        float ls = logf(se);
        for (int o = 0; o < OUTn; o++) out[t*OUTn + o] = s_red[t*OUTn + o] - mx - ls;
    }
}

extern "C" void kernel_launch(void* const* d_in, const int* in_sizes, int n_in,
                              void* d_out, int out_size)
{
    const float* xa  = (const float*)d_in[0];
    const float* fm  = (const float*)d_in[1];
    const int*   nbv = (const int*)  d_in[2];
    // d_in[3] = num_starts (compile-time 64 for this problem)
    const float* ew  = (const float*)d_in[4];
    const float* eb  = (const float*)d_in[5];
    const float* nsw = (const float*)d_in[6];
    const float* nsb = (const float*)d_in[7];
    const float* nmw = (const float*)d_in[8];
    const float* nmb = (const float*)d_in[9];
    const float* aw  = (const float*)d_in[10];
    const float* ab  = (const float*)d_in[11];
    const float* dw  = (const float*)d_in[12];
    const float* db  = (const float*)d_in[13];
    float* out = (float*)d_out;

    cudaFuncSetAttribute(serial_kernel,
                         cudaFuncAttributeMaxDynamicSharedMemorySize, SMEM_BYTES);

    enc_kernel<<<Nn, Hh>>>(xa, ew, eb);
    serial_kernel<<<1, 512, SMEM_BYTES>>>(fm, nbv, nsw, nsb, nmw, nmb,
                                          aw, ab, dw, db, out);
}

// round 4
// speedup vs baseline: 1.1828x; 1.1814x over previous
#include <cuda_runtime.h>

#define Nn      1000
#define INF_    32
#define Hh      128
#define Mm      128
#define DEGc    16
#define Pp      2
#define OUTn    10
#define NSTART  64
#define MAXM    10000
#define QCAP    10016
#define MSGCAP  640
#define THRv    (1.0f - 1e-7f)

typedef unsigned long long ull;
typedef unsigned short u16;

__device__ float g_feats[Nn*Hh];
__device__ float g_msgs[MSGCAP*Mm];

__device__ __forceinline__ ull pack2(float a, float b){
    ull r; asm("mov.b64 %0, {%1,%2};" : "=l"(r) : "f"(a), "f"(b)); return r;
}
__device__ __forceinline__ ull fma2(ull a, ull b, ull c){
    ull d; asm("fma.rn.f32x2 %0, %1, %2, %3;" : "=l"(d) : "l"(a), "l"(b), "l"(c)); return d;
}

__global__ void enc_kernel(const float* __restrict__ xa,
                           const float* __restrict__ ew,
                           const float* __restrict__ eb)
{
    __shared__ float sx[INF_];
    int nrow = blockIdx.x;
    if (threadIdx.x < INF_) sx[threadIdx.x] = xa[nrow*INF_ + threadIdx.x];
    __syncthreads();
    int h = threadIdx.x;
    float a = eb[h];
    #pragma unroll
    for (int i = 0; i < INF_; i++) a = fmaf(sx[i], ew[i*Hh + h], a);
    g_feats[nrow*Hh + h] = a;
}

// ---- shared layout (float units) ----
#define OFF_NSW  0                     // 32768 (256x128 as ull[256][64])
#define OFF_RNS  (OFF_NSW + 256*Hh)    // 2048  (16 rows x 64 ull)
#define OFF_RNM  (OFF_RNS + 2048)      // 2048
#define OFF_X2   (OFF_RNM + 2048)      // 256   (128 ull splatted ns)
#define OFF_AW   (OFF_X2  + 256)       // 256
#define OFF_NSB  (OFF_AW  + 256)       // 128
#define OFF_NMB  (OFF_NSB + 128)       // 128
#define OFF_G    (OFF_NMB + 128)       // 128
#define OFF_ACTP (OFF_G   + 128)       // 16
#define OFF_TACT (OFF_ACTP+ 16)        // 1000
#define OFF_QN   (OFF_TACT+ Nn)        // 5008 floats = 10016 u16
#define OFF_NB   (OFF_QN  + 5008)      // 16 ints
#define OFF_CI   (OFF_NB  + 16)        // 12 ints: head,tail,pc,node,e,done,same,msgsame,key
#define OFF_CF   (OFF_CI  + 12)        // 2 floats: act_b, new_act
#define SMEM_FLOATS (OFF_CF + 4)
#define SMEM_BYTES  (SMEM_FLOATS*4)

__device__ __forceinline__ void scan_q(int l, int curnode,
    const u16* s_qn, const float* s_tact, int* s_ci)
{
    int head = s_ci[0], tail = s_ci[1];
    int lim = tail < MAXM ? tail : MAXM;
    bool found = false;
    while (head < lim) {
        int idx = head + l;
        bool v = idx < lim;
        int nodel = v ? (int)s_qn[idx] : 0;
        float ta = v ? s_tact[nodel] : 2.0f;
        unsigned bal = __ballot_sync(0xffffffffu, v && (ta <= THRv));
        if (bal) {
            int f = __ffs(bal) - 1;
            if (l == f) {
                s_ci[3] = nodel; s_ci[4] = idx;
                s_ci[6] = (nodel == curnode) ? 1 : 0;
                int key = (idx < NSTART) ? idx : (NSTART + ((idx - NSTART) >> 4));
                s_ci[7] = (key == s_ci[8]) ? 1 : 0;
                s_ci[8] = key;
            }
            if (l == 0) s_ci[0] = head + f + 1;
            found = true; break;
        }
        head += 32;
    }
    if (!found && l == 0) s_ci[5] = 1;
}

__global__ void __launch_bounds__(1024, 1) serial_kernel(
    const float* __restrict__ fm,  const int*   __restrict__ nbr,
    const float* __restrict__ nsw, const float* __restrict__ nsb,
    const float* __restrict__ nmw, const float* __restrict__ nmb,
    const float* __restrict__ aw,  const float* __restrict__ ab,
    const float* __restrict__ dw,  const float* __restrict__ db,
    float* __restrict__ out)
{
    extern __shared__ float sm[];
    ull*   s_nsw2 = (ull*)(sm + OFF_NSW);
    float* s_rns  = sm + OFF_RNS;  ull* s_rns2 = (ull*)s_rns;
    float* s_rnm  = sm + OFF_RNM;  ull* s_rnm2 = (ull*)s_rnm;
    ull*   s_x2u  = (ull*)(sm + OFF_X2);
    float* s_aw   = sm + OFF_AW;
    float* s_nsb  = sm + OFF_NSB;
    float* s_nmb  = sm + OFF_NMB;
    float* s_g    = sm + OFF_G;
    float* s_actp = sm + OFF_ACTP;
    float* s_tact = sm + OFF_TACT;
    u16*   s_qn   = (u16*)(sm + OFF_QN);
    int*   s_nb   = (int*)(sm + OFF_NB);
    int*   s_ci   = (int*)(sm + OFF_CI);
    float* s_cf   = sm + OFF_CF;

    const int t  = threadIdx.x;
    const int w  = t >> 5, l = t & 31;
    const int j2 = ((w & 1) << 5) | l;     // pair-column 0..63
    const int rr = w >> 1;                 // k-chunk 0..15 (16 inputs each)
    const int i16 = l & 15;

    // ---- init ----
    for (int i = t; i < (256*Hh)/4; i += 1024)
        ((float4*)(sm + OFF_NSW))[i] = ((const float4*)nsw)[i];
    if (t < 256) s_aw[t] = aw[t];
    if (t < 128) { s_nsb[t] = nsb[t]; s_nmb[t] = nmb[t]; s_g[t] = 0.f; }
    if (t < Nn)  s_tact[t] = 0.f;
    if (t < NSTART) s_qn[t] = (u16)t;
    if (t == 0) {
        s_ci[0] = 0; s_ci[1] = NSTART; s_ci[2] = 0; s_ci[5] = 0; s_ci[8] = -1;
        s_cf[0] = ab[0];
    }
    // nm_w rows [16rr,16rr+16) in registers as f32x2
    ull wnm[16];
    #pragma unroll
    for (int i = 0; i < 16; i++) {
        const float2 v = *(const float2*)(nmw + (16*rr + i)*Hh + 2*j2);
        wnm[i] = pack2(v.x, v.y);
    }
    __syncthreads();
    if (w == 0) scan_q(l, -1, s_qn, s_tact, s_ci);
    __syncthreads();

    while (!s_ci[5]) {
        const int node = s_ci[3], e = s_ci[4], pc = s_ci[2], tail = s_ci[1];
        const int same = s_ci[6], msgsame = s_ci[7];

        // ---- ph1: NS partials (+ msg recompute on key change) + act + nbr ----
        if (rr < 8) {
            const int k = 16*rr + i16;
            float xg = 0.f;
            if (l < 16) xg = same ? sm[OFF_X2 + 2*k] : g_feats[node*Hh + k];
            ull acc = 0ull;
            const ull* wb = s_nsw2 + (size_t)(16*rr)*64 + j2;
            #pragma unroll
            for (int kk = 0; kk < 16; kk++) {
                float xk = __shfl_sync(0xffffffffu, xg, kk);
                acc = fma2(pack2(xk, xk), wb[kk*64], acc);
            }
            s_rns2[rr*64 + j2] = acc;
            float ap = (l < 16) ? xg * s_aw[k] : 0.f;
            #pragma unroll
            for (int o = 16; o; o >>= 1) ap += __shfl_xor_sync(0xffffffffu, ap, o);
            if (l == 0) s_actp[rr] = ap;
        } else {
            if (!msgsame) {
                const int kp = 16*(rr - 8) + i16;          // msg element
                float xg = 0.f;
                if (l < 16) {
                    const float* mp = (e < NSTART) ? (fm + e*Mm)
                                                   : (g_msgs + ((e - NSTART) >> 4)*Mm);
                    xg = mp[kp];
                }
                ull acc = 0ull, acc2 = 0ull;
                const ull* wb = s_nsw2 + (size_t)(Hh + 16*(rr - 8))*64 + j2;
                #pragma unroll
                for (int kk = 0; kk < 16; kk++) {
                    float xk = __shfl_sync(0xffffffffu, xg, kk);
                    ull xs = pack2(xk, xk);
                    acc  = fma2(xs, wb[kk*64], acc);
                    acc2 = fma2(xs, wnm[kk], acc2);
                }
                s_rns2[rr*64 + j2] = acc;
                s_rnm2[rr*64 + j2] = acc2;
                float ap = (l < 16) ? xg * s_aw[Hh + kp] : 0.f;
                #pragma unroll
                for (int o = 16; o; o >>= 1) ap += __shfl_xor_sync(0xffffffffu, ap, o);
                if (l == 0) s_actp[rr] = ap;
            }
            if (w == 31 && l < DEGc) s_nb[l] = nbr[node*DEGc + l];
        }
        __syncthreads();

        // ---- ph2: ns reduce -> relu -> splat ; act finalize ; enqueue ----
        if (t < 128) {
            float v = s_nsb[t];
            #pragma unroll
            for (int q = 0; q < 16; q++) v += s_rns[q*128 + t];
            v = fmaxf(v, 0.f);
            s_x2u[t] = pack2(v, v);
        } else if (t == 128) {
            float z = s_cf[0];
            #pragma unroll
            for (int q = 0; q < 16; q++) z += s_actp[q];
            float cand = 1.f / (1.f + expf(-z));
            float ta = s_tact[node];
            float na = (ta + cand > 1.0f) ? (1.0f - ta) : cand;
            s_cf[1] = na;
            s_tact[node] = ta + na;
        } else if (w == 5 && l < DEGc) {
            int idx = tail + l;
            if (idx < QCAP) s_qn[idx] = (u16)s_nb[l];
        } else if (t == 192) {
            s_ci[1] = tail + DEGc;
            s_ci[2] = pc + 1;
        }
        __syncthreads();

        // ---- ph3: NM ns-half partials ; scan (warp 16) ----
        if (rr < 8) {
            ull acc = 0ull;
            const ull* xs = s_x2u + 16*rr;
            #pragma unroll
            for (int kk = 0; kk < 16; kk++)
                acc = fma2(xs[kk], wnm[kk], acc);          // uniform LDS.64 broadcast
            s_rnm2[rr*64 + j2] = acc;
        } else if (w == 16) {
            scan_q(l, node, s_qn, s_tact, s_ci);
        }
        __syncthreads();

        // ---- ph4: commit message / feats / readout ----
        if (t < 128) {
            if (pc < MSGCAP) {
                float v = s_nmb[t];
                #pragma unroll
                for (int q = 0; q < 16; q++) v += s_rnm[q*128 + t];
                g_msgs[pc*Mm + t] = v;
            }
        } else if (t < 256) {
            int idx = t - 128;
            float nsv = sm[OFF_X2 + 2*idx];
            g_feats[node*Hh + idx] = nsv;
            s_g[idx] += nsv * s_cf[1];
        }
        __syncthreads();
    }

    // ---- decode + log_softmax ----
    if (t < Pp*OUTn) {
        int p = t / OUTn, o = t % OUTn;
        float z = db[p*OUTn + o];
        #pragma unroll 8
        for (int h = 0; h < Hh; h++) z = fmaf(s_g[h], dw[(p*Hh + h)*OUTn + o], z);
        s_rns[t] = z;
    }
    __syncthreads();
    if (t < Pp) {
        float mx = -1e30f;
        for (int o = 0; o < OUTn; o++) mx = fmaxf(mx, s_rns[t*OUTn + o]);
        float se = 0.f;
        for (int o = 0; o < OUTn; o++) se += expf(s_rns[t*OUTn + o] - mx);
        float ls = logf(se);
        for (int o = 0; o < OUTn; o++) out[t*OUTn + o] = s_rns[t*OUTn + o] - mx - ls;
    }
}

extern "C" void kernel_launch(void* const* d_in, const int* in_sizes, int n_in,
                              void* d_out, int out_size)
{
    const float* xa  = (const float*)d_in[0];
    const float* fm  = (const float*)d_in[1];
    const int*   nbv = (const int*)  d_in[2];
    const float* ew  = (const float*)d_in[4];
    const float* eb  = (const float*)d_in[5];
    const float* nsw = (const float*)d_in[6];
    const float* nsb = (const float*)d_in[7];
    const float* nmw = (const float*)d_in[8];
    const float* nmb = (const float*)d_in[9];
    const float* aw  = (const float*)d_in[10];
    const float* ab  = (const float*)d_in[11];
    const float* dw  = (const float*)d_in[12];
    const float* db  = (const float*)d_in[13];
    float* out = (float*)d_out;

    cudaFuncSetAttribute(serial_kernel,
                         cudaFuncAttributeMaxDynamicSharedMemorySize, SMEM_BYTES);

    enc_kernel<<<Nn, Hh>>>(xa, ew, eb);
    serial_kernel<<<1, 1024, SMEM_BYTES>>>(fm, nbv, nsw, nsb, nmw, nmb,
                                           aw, ab, dw, db, out);
}